// round 5
// baseline (speedup 1.0000x reference)
#include <cuda_runtime.h>

#define KSEL 8
#define NB   16384
#define BQ   65536
#define FDIM 64
#define EPSF 1e-8f
#define INV_TEMP 200.0f   // 1 / (2*0.05*0.05)

#define TILE 2048
#define TPB  64

typedef unsigned long long u64;

// SoA anchors, positions pre-negated so dx = cx + (-px) is one packed add.
__device__ float g_npx[NB];
__device__ float g_npy[NB];
__device__ float g_npz[NB];
__device__ float g_wa [NB];

__global__ void prep_kernel(const float* __restrict__ pos,
                            const float* __restrict__ w) {
    int i = blockIdx.x * blockDim.x + threadIdx.x;
    if (i < NB) {
        float wi = w[i];
        g_npx[i] = -pos[3 * i + 0];
        g_npy[i] = -pos[3 * i + 1];
        g_npz[i] = -pos[3 * i + 2];
        g_wa [i] = 1.0f / (wi * wi + EPSF);
    }
}

// ---- packed f32x2 helpers (Blackwell sm_100a) ----
__device__ __forceinline__ u64 pk2(float lo, float hi) {
    u64 r; asm("mov.b64 %0, {%1, %2};" : "=l"(r) : "f"(lo), "f"(hi)); return r;
}
__device__ __forceinline__ void unpk2(u64 v, float& lo, float& hi) {
    asm("mov.b64 {%0, %1}, %2;" : "=f"(lo), "=f"(hi) : "l"(v));
}
__device__ __forceinline__ u64 add2(u64 a, u64 b) {
    u64 r; asm("add.rn.f32x2 %0, %1, %2;" : "=l"(r) : "l"(a), "l"(b)); return r;
}
__device__ __forceinline__ u64 mul2(u64 a, u64 b) {
    u64 r; asm("mul.rn.f32x2 %0, %1, %2;" : "=l"(r) : "l"(a), "l"(b)); return r;
}
__device__ __forceinline__ u64 fma2(u64 a, u64 b, u64 c) {
    u64 r; asm("fma.rn.f32x2 %0, %1, %2, %3;" : "=l"(r) : "l"(a), "l"(b), "l"(c)); return r;
}

__device__ __forceinline__ void ins8(float sq, int jj, float d[KSEL], int id[KSEL], float& worst) {
    if (sq < worst) {
        d[KSEL - 1]  = sq;
        id[KSEL - 1] = jj;
#pragma unroll
        for (int k = KSEL - 1; k > 0; --k) {
            if (d[k] < d[k - 1]) {
                float td = d[k]; d[k] = d[k - 1]; d[k - 1] = td;
                int   ti = id[k]; id[k] = id[k - 1]; id[k - 1] = ti;
            }
        }
        worst = d[KSEL - 1];
    }
}

__global__ __launch_bounds__(TPB) void knn_kernel(
    const float* __restrict__ coords,
    const float* __restrict__ features,
    float* __restrict__ out)
{
    __shared__ union SMem {
        struct {
            float px[TILE]; float py[TILE]; float pz[TILE]; float wa[TILE];
        } s;                                    // 32 KB
        struct {
            int   idx[TPB][KSEL];               // 2 KB
            float w[TPB][KSEL];                 // 2 KB
        } ep;
    } sm;

    const int tid = threadIdx.x;
    const int q = blockIdx.x * TPB + tid;
    const float cx = coords[3 * q + 0];
    const float cy = coords[3 * q + 1];
    const float cz = coords[3 * q + 2];
    const u64 cx2 = pk2(cx, cx);
    const u64 cy2 = pk2(cy, cy);
    const u64 cz2 = pk2(cz, cz);

    float d[KSEL];
    int   id[KSEL];
#pragma unroll
    for (int k = 0; k < KSEL; ++k) { d[k] = 3.4e38f; id[k] = 0; }

    for (int t0 = 0; t0 < NB; t0 += TILE) {
        __syncthreads();
#pragma unroll
        for (int j = tid * 4; j < TILE; j += TPB * 4) {
            *(float4*)&sm.s.px[j] = *(const float4*)&g_npx[t0 + j];
            *(float4*)&sm.s.py[j] = *(const float4*)&g_npy[t0 + j];
            *(float4*)&sm.s.pz[j] = *(const float4*)&g_npz[t0 + j];
            *(float4*)&sm.s.wa[j] = *(const float4*)&g_wa [t0 + j];
        }
        __syncthreads();

        const ulonglong2* px2 = (const ulonglong2*)sm.s.px;
        const ulonglong2* py2 = (const ulonglong2*)sm.s.py;
        const ulonglong2* pz2 = (const ulonglong2*)sm.s.pz;
        const ulonglong2* wa2 = (const ulonglong2*)sm.s.wa;

        float worst = d[KSEL - 1];
#pragma unroll 2
        for (int j4 = 0; j4 < TILE / 4; ++j4) {
            ulonglong2 vx = px2[j4];
            ulonglong2 vy = py2[j4];
            ulonglong2 vz = pz2[j4];
            ulonglong2 vw = wa2[j4];

            u64 dx01 = add2(cx2, vx.x), dx23 = add2(cx2, vx.y);
            u64 dy01 = add2(cy2, vy.x), dy23 = add2(cy2, vy.y);
            u64 dz01 = add2(cz2, vz.x), dz23 = add2(cz2, vz.y);

            u64 s01 = mul2(fma2(dz01, dz01, fma2(dy01, dy01, mul2(dx01, dx01))), vw.x);
            u64 s23 = mul2(fma2(dz23, dz23, fma2(dy23, dy23, mul2(dx23, dx23))), vw.y);

            float f0, f1, f2, f3;
            unpk2(s01, f0, f1);
            unpk2(s23, f2, f3);
            float m = fminf(fminf(f0, f1), fminf(f2, f3));
            if (m < worst) {
                const int jb = t0 + j4 * 4;
                ins8(f0, jb + 0, d, id, worst);
                ins8(f1, jb + 1, d, id, worst);
                ins8(f2, jb + 2, d, id, worst);
                ins8(f3, jb + 3, d, id, worst);
            }
        }
    }

    // Softmax over the 8 selected (logit = -sq * INV_TEMP), max-subtracted.
    float m0 = d[0];
    float wk[KSEL];
    float wsum = 0.0f;
#pragma unroll
    for (int k = 0; k < KSEL; ++k) {
        wk[k] = __expf((m0 - d[k]) * INV_TEMP);
        wsum += wk[k];
    }
    float inv = 1.0f / wsum;

    __syncthreads();   // everyone done reading anchor tile before overwrite
#pragma unroll
    for (int k = 0; k < KSEL; ++k) {
        sm.ep.w[tid][k]   = wk[k] * inv;
        sm.ep.idx[tid][k] = id[k];
    }
    __syncthreads();

    // Cooperative gather: each warp produces the 64-float output rows of its
    // 32 queries; lane L accumulates features [2L, 2L+1] (float2, coalesced).
    const int lane = tid & 31;
    const int warp = tid >> 5;
    for (int qq = 0; qq < 32; ++qq) {
        const int tq = warp * 32 + qq;
        float2 acc = make_float2(0.0f, 0.0f);
#pragma unroll
        for (int k = 0; k < KSEL; ++k) {
            const int   ii = sm.ep.idx[tq][k];
            const float ww = sm.ep.w[tq][k];
            float2 f = ((const float2*)(features + (size_t)ii * FDIM))[lane];
            acc.x = fmaf(ww, f.x, acc.x);
            acc.y = fmaf(ww, f.y, acc.y);
        }
        const int gq = blockIdx.x * TPB + tq;
        ((float2*)out)[gq * 32 + lane] = acc;
    }
}

extern "C" void kernel_launch(void* const* d_in, const int* in_sizes, int n_in,
                              void* d_out, int out_size) {
    const float* coords    = (const float*)d_in[0];
    const float* positions = (const float*)d_in[1];
    const float* weights   = (const float*)d_in[2];
    const float* features  = (const float*)d_in[3];
    float* out = (float*)d_out;

    prep_kernel<<<NB / 256, 256>>>(positions, weights);
    knn_kernel<<<BQ / TPB, TPB>>>(coords, features, out);
}

// round 6
// speedup vs baseline: 1.3125x; 1.3125x over previous
#include <cuda_runtime.h>

#define KSEL 8
#define NB   16384
#define BQ   65536
#define FDIM 64
#define EPSF 1e-8f
#define INV_TEMP 200.0f   // 1 / (2*0.05*0.05)

#define TILE 1024
#define TPB  64

// Packed anchors: {px, py, pz, inv_w2}
__device__ float4 g_pack[NB];

__global__ void prep_kernel(const float* __restrict__ pos,
                            const float* __restrict__ w) {
    int i = blockIdx.x * blockDim.x + threadIdx.x;
    if (i < NB) {
        float wi = w[i];
        float a = 1.0f / (wi * wi + EPSF);
        g_pack[i] = make_float4(pos[3 * i + 0], pos[3 * i + 1], pos[3 * i + 2], a);
    }
}

__device__ __forceinline__ void ins8(float sq, int jj, float d[KSEL], int id[KSEL], float& worst) {
    if (sq < worst) {
        d[KSEL - 1]  = sq;
        id[KSEL - 1] = jj;
#pragma unroll
        for (int k = KSEL - 1; k > 0; --k) {
            if (d[k] < d[k - 1]) {
                float td = d[k]; d[k] = d[k - 1]; d[k - 1] = td;
                int   ti = id[k]; id[k] = id[k - 1]; id[k - 1] = ti;
            }
        }
        worst = d[KSEL - 1];
    }
}

__global__ __launch_bounds__(TPB) void knn_kernel(
    const float* __restrict__ coords,
    const float* __restrict__ features,
    float* __restrict__ out)
{
    // Anchor tile and epilogue handoff share the same shared memory.
    __shared__ union SMem {
        float4 anch[TILE];                      // 16 KB
        struct {
            int   idx[TPB][KSEL];               // 2 KB
            float w[TPB][KSEL];                 // 2 KB
        } ep;
    } sm;

    const int tid = threadIdx.x;
    const int q = blockIdx.x * TPB + tid;
    const float cx = coords[3 * q + 0];
    const float cy = coords[3 * q + 1];
    const float cz = coords[3 * q + 2];

    float d[KSEL];
    int   id[KSEL];
#pragma unroll
    for (int k = 0; k < KSEL; ++k) { d[k] = 3.4e38f; id[k] = 0; }

    for (int t0 = 0; t0 < NB; t0 += TILE) {
        __syncthreads();
#pragma unroll
        for (int j = tid; j < TILE; j += TPB)
            sm.anch[j] = g_pack[t0 + j];
        __syncthreads();

        float worst = d[KSEL - 1];
#pragma unroll 2
        for (int j4 = 0; j4 < TILE; j4 += 4) {
            // 4 independent distance chains -> ILP; one rare branch per 4.
            float4 p0 = sm.anch[j4 + 0];
            float4 p1 = sm.anch[j4 + 1];
            float4 p2 = sm.anch[j4 + 2];
            float4 p3 = sm.anch[j4 + 3];

            float dx0 = cx - p0.x, dy0 = cy - p0.y, dz0 = cz - p0.z;
            float dx1 = cx - p1.x, dy1 = cy - p1.y, dz1 = cz - p1.z;
            float dx2 = cx - p2.x, dy2 = cy - p2.y, dz2 = cz - p2.z;
            float dx3 = cx - p3.x, dy3 = cy - p3.y, dz3 = cz - p3.z;

            float s0 = fmaf(dz0, dz0, fmaf(dy0, dy0, dx0 * dx0)) * p0.w;
            float s1 = fmaf(dz1, dz1, fmaf(dy1, dy1, dx1 * dx1)) * p1.w;
            float s2 = fmaf(dz2, dz2, fmaf(dy2, dy2, dx2 * dx2)) * p2.w;
            float s3 = fmaf(dz3, dz3, fmaf(dy3, dy3, dx3 * dx3)) * p3.w;

            float m = fminf(fminf(s0, s1), fminf(s2, s3));
            if (m < worst) {
                const int jb = t0 + j4;
                ins8(s0, jb + 0, d, id, worst);
                ins8(s1, jb + 1, d, id, worst);
                ins8(s2, jb + 2, d, id, worst);
                ins8(s3, jb + 3, d, id, worst);
            }
        }
    }

    // Softmax over the 8 selected (logit = -sq * INV_TEMP), max-subtracted.
    float m0 = d[0];
    float wk[KSEL];
    float wsum = 0.0f;
#pragma unroll
    for (int k = 0; k < KSEL; ++k) {
        wk[k] = __expf((m0 - d[k]) * INV_TEMP);
        wsum += wk[k];
    }
    float inv = 1.0f / wsum;

    __syncthreads();   // everyone done reading anchor tile before overwrite
#pragma unroll
    for (int k = 0; k < KSEL; ++k) {
        sm.ep.w[tid][k]   = wk[k] * inv;
        sm.ep.idx[tid][k] = id[k];
    }
    __syncthreads();

    // Cooperative gather: each warp produces the 64-float output rows of its
    // 32 queries; lane L accumulates features [2L, 2L+1] (float2, coalesced).
    const int lane = tid & 31;
    const int warp = tid >> 5;
    for (int qq = 0; qq < 32; ++qq) {
        const int tq = warp * 32 + qq;
        float2 acc = make_float2(0.0f, 0.0f);
#pragma unroll
        for (int k = 0; k < KSEL; ++k) {
            const int   ii = sm.ep.idx[tq][k];
            const float ww = sm.ep.w[tq][k];
            float2 f = ((const float2*)(features + (size_t)ii * FDIM))[lane];
            acc.x = fmaf(ww, f.x, acc.x);
            acc.y = fmaf(ww, f.y, acc.y);
        }
        const int gq = blockIdx.x * TPB + tq;
        ((float2*)out)[gq * 32 + lane] = acc;
    }
}

extern "C" void kernel_launch(void* const* d_in, const int* in_sizes, int n_in,
                              void* d_out, int out_size) {
    const float* coords    = (const float*)d_in[0];
    const float* positions = (const float*)d_in[1];
    const float* weights   = (const float*)d_in[2];
    const float* features  = (const float*)d_in[3];
    float* out = (float*)d_out;

    prep_kernel<<<NB / 256, 256>>>(positions, weights);
    knn_kernel<<<BQ / TPB, TPB>>>(coords, features, out);
}